// round 13
// baseline (speedup 1.0000x reference)
#include <cuda_runtime.h>
#include <cuda_bf16.h>
#include <math.h>

// ChainCRF: B=128, S=256, C=64.
// TWO WARPS per batch row (128 CTAs x 64 threads). Thread j owns column j.
// Linear-domain forward recursion; log taken once at the end.
// Power-of-two renorm every 4 steps; 8-step unrolled chunks with a 2-chunk
// deep LDG->MUFU prefetch ring (raws for chunk t+16 and exps for chunk t+8
// produced during chunk t). Per step: 16 broadcast LDS.128, 32 fma.rn.f32x2
// in four chains, STS.32, one __syncthreads.

#define Bc 128
#define Sc 256
#define Cc 64
#define Tc 64

__device__ float g_batch_res[Bc];
__device__ unsigned int g_ticket = 0;

#define FMA2(d,a,b,c)  asm("fma.rn.f32x2 %0, %1, %2, %3;" : "=l"(d) : "l"(a), "l"(b), "l"(c))
#define ADD2(d,a,b)    asm("add.rn.f32x2 %0, %1, %2;" : "=l"(d) : "l"(a), "l"(b))
#define PACK2(d,lo,hi) asm("mov.b64 %0, {%1, %2};" : "=l"(d) : "f"(lo), "f"(hi))
#define UNPACK2(lo,hi,s) asm("mov.b64 {%0, %1}, %2;" : "=f"(lo), "=f"(hi) : "l"(s))

// Core step: q_new[j] = (sum_i q_i * expU[i][j]) * EMXV.  4 accumulator chains.
#define STEP_CORE(QR, QW, EMXV) do {                                           \
    unsigned long long _a0 = 0ull, _a1 = 0ull, _a2 = 0ull, _a3 = 0ull;         \
    const ulonglong2* _qv = (const ulonglong2*)(QR);                           \
    _Pragma("unroll")                                                          \
    for (int _c = 0; _c < 8; ++_c) {                                           \
        ulonglong2 _v = _qv[2 * _c];                                           \
        ulonglong2 _w = _qv[2 * _c + 1];                                       \
        FMA2(_a0, _v.x, rE[4*_c+0], _a0);                                      \
        FMA2(_a1, _v.y, rE[4*_c+1], _a1);                                      \
        FMA2(_a2, _w.x, rE[4*_c+2], _a2);                                      \
        FMA2(_a3, _w.y, rE[4*_c+3], _a3);                                      \
    }                                                                          \
    ADD2(_a0, _a0, _a1);                                                       \
    ADD2(_a2, _a2, _a3);                                                       \
    ADD2(_a0, _a0, _a2);                                                       \
    float _lo, _hi;                                                            \
    UNPACK2(_lo, _hi, _a0);                                                    \
    (QW)[j] = (_lo + _hi) * (EMXV);                                            \
    __syncthreads();                                                           \
} while (0)

// Renormalizing step: exponent of q[0], exact 2^-k folded into EMX.
#define STEP_R(QR, QW, EX) do {                                                \
    float _q0 = (QR)[0];                                                       \
    int   _k  = (int)((__float_as_uint(_q0) >> 23) & 0xFF) - 127;              \
    K += _k;                                                                   \
    float _emx = (EX) * __uint_as_float((unsigned)(127 - _k) << 23);           \
    STEP_CORE(QR, QW, _emx);                                                   \
} while (0)

#define STEP_N(QR, QW, EX) STEP_CORE(QR, QW, (EX))

__global__ __launch_bounds__(Tc, 1)
void crf_kernel(const float* __restrict__ em,
                const int*   __restrict__ tags,
                const float* __restrict__ mask,
                const float* __restrict__ U,
                float* __restrict__ out)
{
    const int b = blockIdx.x;
    const int j = threadIdx.x;           // column owned by this thread (0..63)
    const int l = j & 31;                // lane
    const int w = j >> 5;                // warp (0,1)

    __shared__ __align__(16) float qA[Cc];
    __shared__ __align__(16) float qB[Cc];
    __shared__ __align__(16) float sU[Cc * Cc];
    __shared__ __align__(16) int   stags[Sc];
    __shared__ __align__(16) float smask[Sc];
    __shared__ float red[2];

    // ---- stage U, tags, mask into smem (coalesced) ----
    {
        const float4* U4  = (const float4*)U;
        float4*       sU4 = (float4*)sU;
#pragma unroll
        for (int i = 0; i < (Cc * Cc / 4) / Tc; ++i)     // 16 iters
            sU4[j + Tc * i] = U4[j + Tc * i];

        ((int4*)stags)[j]  = ((const int4*)(tags + (size_t)b * Sc))[j];
        ((float4*)smask)[j] = ((const float4*)(mask + (size_t)b * Sc))[j];
    }
    __syncthreads();

    // ---- expU column j packed over i-pairs: 32 u64 registers ----
    unsigned long long rE[32];
#pragma unroll
    for (int p = 0; p < 32; ++p) {
        float e0 = __expf(sU[(2 * p + 0) * Cc + j]);
        float e1 = __expf(sU[(2 * p + 1) * Cc + j]);
        PACK2(rE[p], e0, e1);            // {E[2p][j], E[2p+1][j]}
    }

    const float* emb = em + (size_t)b * Sc * Cc;   // em[t][j] = emb[t*64 + j]

    // mask uniformity check (hoists the branch out of the hot loop)
    int ok = 1;
#pragma unroll
    for (int t = j; t < Sc; t += Tc) ok &= (smask[t] == 1.0f);
    ok = __syncthreads_and(ok);

    // q(0) = exp(em[0])
    qA[j] = __expf(emb[j]);
    int K = 0;
    __syncthreads();

    if (ok) {
        // ---- fast path: 8-step chunks, renorm every 4 steps ----
        // Prologue: steps 1..7 with directly computed exps; preload
        // ex[] (chunk 8) and raw[] (chunk 16).
        float x1 = __expf(emb[1 * Cc + j]);
        float x2 = __expf(emb[2 * Cc + j]);
        float x3 = __expf(emb[3 * Cc + j]);
        float x4 = __expf(emb[4 * Cc + j]);
        float x5 = __expf(emb[5 * Cc + j]);
        float x6 = __expf(emb[6 * Cc + j]);
        float x7 = __expf(emb[7 * Cc + j]);

        float e0 = __expf(emb[ 8 * Cc + j]);
        float e1 = __expf(emb[ 9 * Cc + j]);
        float e2 = __expf(emb[10 * Cc + j]);
        float e3 = __expf(emb[11 * Cc + j]);
        float e4 = __expf(emb[12 * Cc + j]);
        float e5 = __expf(emb[13 * Cc + j]);
        float e6 = __expf(emb[14 * Cc + j]);
        float e7 = __expf(emb[15 * Cc + j]);

        float r0 = emb[16 * Cc + j], r1 = emb[17 * Cc + j];
        float r2 = emb[18 * Cc + j], r3 = emb[19 * Cc + j];
        float r4 = emb[20 * Cc + j], r5 = emb[21 * Cc + j];
        float r6 = emb[22 * Cc + j], r7 = emb[23 * Cc + j];

        STEP_R(qA, qB, x1);              // t=1 (renorm)
        STEP_N(qB, qA, x2);              // t=2
        STEP_N(qA, qB, x3);              // t=3
        STEP_R(qB, qA, x4);              // t=4 (renorm)
        STEP_N(qA, qB, x5);              // t=5
        STEP_N(qB, qA, x6);              // t=6
        STEP_N(qA, qB, x7);              // t=7  -> q in qB

        // Chunks t=8,16,...,248. Invariant at loop head:
        //   q in qB; e0..e7 = exp(em[t..t+7]); r0..r7 = em[t+8..t+15].
#pragma unroll 1
        for (int t = 8; t < Sc; t += 8) {
            // exps for chunk t+8 (one MUFU batch, off-chain)
            float f0 = __expf(r0), f1 = __expf(r1);
            float f2 = __expf(r2), f3 = __expf(r3);
            float f4 = __expf(r4), f5 = __expf(r5);
            float f6 = __expf(r6), f7 = __expf(r7);
            // raws for chunk t+16 (MLP-8 LDG burst, off-chain)
            int tb = t + 16;
            float g0 = (tb + 0 < Sc) ? emb[(tb + 0) * Cc + j] : 0.0f;
            float g1 = (tb + 1 < Sc) ? emb[(tb + 1) * Cc + j] : 0.0f;
            float g2 = (tb + 2 < Sc) ? emb[(tb + 2) * Cc + j] : 0.0f;
            float g3 = (tb + 3 < Sc) ? emb[(tb + 3) * Cc + j] : 0.0f;
            float g4 = (tb + 4 < Sc) ? emb[(tb + 4) * Cc + j] : 0.0f;
            float g5 = (tb + 5 < Sc) ? emb[(tb + 5) * Cc + j] : 0.0f;
            float g6 = (tb + 6 < Sc) ? emb[(tb + 6) * Cc + j] : 0.0f;
            float g7 = (tb + 7 < Sc) ? emb[(tb + 7) * Cc + j] : 0.0f;

            STEP_R(qB, qA, e0);          // t   (renorm)
            STEP_N(qA, qB, e1);
            STEP_N(qB, qA, e2);
            STEP_N(qA, qB, e3);
            STEP_R(qB, qA, e4);          // t+4 (renorm)
            STEP_N(qA, qB, e5);
            STEP_N(qB, qA, e6);
            STEP_N(qA, qB, e7);          // -> q back in qB

            e0 = f0; e1 = f1; e2 = f2; e3 = f3;
            e4 = f4; e5 = f5; e6 = f6; e7 = f7;
            r0 = g0; r1 = g1; r2 = g2; r3 = g3;
            r4 = g4; r5 = g5; r6 = g6; r7 = g7;
        }
        // t=255 wrote qB
    } else {
        // ---- generic masked fallback (never taken in this dataset) ----
        const float* qr = qA; float* qw = qB;
        for (int t = 1; t < Sc; ++t) {
            float m   = smask[t];
            float emv = emb[t * Cc + j];
            float q0  = qr[0];
            int   k   = (int)((__float_as_uint(q0) >> 23) & 0xFF) - 127;
            float sc  = __uint_as_float((unsigned)(127 - k) << 23);
            K += k;

            float s;
            if (m == 1.0f) {
                float a = 0.f;
                for (int i = 0; i < Cc; ++i)
                    a = fmaf(qr[i], __expf(sU[i * Cc + j]), a);
                s = a * __expf(emv);
            } else if (m == 0.0f) {
                float a = 0.f;
                for (int i = 0; i < Cc; ++i) a += qr[i];
                s = a;
            } else {
                float a = 0.f;
                for (int i = 0; i < Cc; ++i)
                    a += qr[i] * __expf((emv + sU[i * Cc + j]) * m);
                s = a;
            }
            qw[j] = s * sc;
            __syncthreads();
            const float* tr = qr; qr = qw; qw = const_cast<float*>(tr);
        }
        // t=255 (odd) wrote qB
    }

    // ---- path energy ----
    float pe = 0.0f;
#pragma unroll
    for (int t = j; t < Sc; t += Tc) {
        float mt = smask[t];
        int   tg = stags[t];
        int   tm = (int)((float)tg * mt);
        pe += emb[t * Cc + tm] * mt;
    }
#pragma unroll
    for (int t = 1 + j; t < Sc; t += Tc) {
        pe += sU[stags[t - 1] * Cc + stags[t]] * smask[t];
    }
#pragma unroll
    for (int o = 16; o > 0; o >>= 1)
        pe += __shfl_xor_sync(0xFFFFFFFFu, pe, o);
    if (l == 0) red[w] = pe;
    __syncthreads();

    // ---- free energy + per-batch result + fused finalize ----
    if (j == 0) {
        float qs = 0.0f;
#pragma unroll
        for (int i = 0; i < Cc; ++i) qs += qB[i];
        float fe = logf(qs) + (float)K * 0.6931471805599453f;
        g_batch_res[b] = fe - (red[0] + red[1]);
        __threadfence();
    }
    __syncthreads();

    if (w == 0) {
        unsigned int old = 0;
        if (l == 0) old = atomicAdd(&g_ticket, 1u);
        old = __shfl_sync(0xFFFFFFFFu, old, 0);
        if (old == Bc - 1) {
            __threadfence();
            float v = 0.0f;
#pragma unroll
            for (int i = 0; i < Bc / 32; ++i) v += g_batch_res[l + 32 * i];
#pragma unroll
            for (int o = 16; o > 0; o >>= 1)
                v += __shfl_xor_sync(0xFFFFFFFFu, v, o);
            if (l == 0) {
                out[0] = v * (1.0f / (float)Bc);
                g_ticket = 0;              // reset for next graph replay
            }
        }
    }
}

extern "C" void kernel_launch(void* const* d_in, const int* in_sizes, int n_in,
                              void* d_out, int out_size)
{
    const float* emissions = (const float*)d_in[0];
    const int*   true_tags = (const int*)  d_in[1];
    const float* mask      = (const float*)d_in[2];
    const float* U         = (const float*)d_in[3];
    float* out = (float*)d_out;

    crf_kernel<<<Bc, Tc>>>(emissions, true_tags, mask, U, out);
}

// round 14
// speedup vs baseline: 1.1239x; 1.1239x over previous
#include <cuda_runtime.h>
#include <cuda_bf16.h>
#include <math.h>

// ChainCRF: B=128, S=256, C=64.
// TWO WARPS per batch row (128 CTAs x 64 threads). Thread j owns column j.
// Linear-domain forward recursion; power-of-two renorm every 4 steps folded
// into that step's emission multiplier; log taken once at the end.
// Hot loop (R12): per step 16 broadcast LDS.128, 32 fma.rn.f32x2 in four
// chains, STS.32, one __syncthreads. Prologue latency-trimmed: rE built
// straight from global U concurrent with smem staging; ONE pre-loop barrier.

#define Bc 128
#define Sc 256
#define Cc 64
#define Tc 64

__device__ float g_batch_res[Bc];
__device__ unsigned int g_ticket = 0;

#define FMA2(d,a,b,c)  asm("fma.rn.f32x2 %0, %1, %2, %3;" : "=l"(d) : "l"(a), "l"(b), "l"(c))
#define ADD2(d,a,b)    asm("add.rn.f32x2 %0, %1, %2;" : "=l"(d) : "l"(a), "l"(b))
#define PACK2(d,lo,hi) asm("mov.b64 %0, {%1, %2};" : "=l"(d) : "f"(lo), "f"(hi))
#define UNPACK2(lo,hi,s) asm("mov.b64 {%0, %1}, %2;" : "=f"(lo), "=f"(hi) : "l"(s))

// Core step: q_new[j] = (sum_i q_i * expU[i][j]) * EMXV.  4 accumulator chains.
#define STEP_CORE(QR, QW, EMXV) do {                                           \
    unsigned long long _a0 = 0ull, _a1 = 0ull, _a2 = 0ull, _a3 = 0ull;         \
    const ulonglong2* _qv = (const ulonglong2*)(QR);                           \
    _Pragma("unroll")                                                          \
    for (int _c = 0; _c < 8; ++_c) {                                           \
        ulonglong2 _v = _qv[2 * _c];                                           \
        ulonglong2 _w = _qv[2 * _c + 1];                                       \
        FMA2(_a0, _v.x, rE[4*_c+0], _a0);                                      \
        FMA2(_a1, _v.y, rE[4*_c+1], _a1);                                      \
        FMA2(_a2, _w.x, rE[4*_c+2], _a2);                                      \
        FMA2(_a3, _w.y, rE[4*_c+3], _a3);                                      \
    }                                                                          \
    ADD2(_a0, _a0, _a1);                                                       \
    ADD2(_a2, _a2, _a3);                                                       \
    ADD2(_a0, _a0, _a2);                                                       \
    float _lo, _hi;                                                            \
    UNPACK2(_lo, _hi, _a0);                                                    \
    (QW)[j] = (_lo + _hi) * (EMXV);                                            \
    __syncthreads();                                                           \
} while (0)

// Renormalizing step: exponent of q[0], exact 2^-k folded into EMX.
#define STEP_R(QR, QW, EX) do {                                                \
    float _q0 = (QR)[0];                                                       \
    int   _k  = (int)((__float_as_uint(_q0) >> 23) & 0xFF) - 127;              \
    K += _k;                                                                   \
    float _emx = (EX) * __uint_as_float((unsigned)(127 - _k) << 23);           \
    STEP_CORE(QR, QW, _emx);                                                   \
} while (0)

#define STEP_N(QR, QW, EX) STEP_CORE(QR, QW, (EX))

__global__ __launch_bounds__(Tc, 1)
void crf_kernel(const float* __restrict__ em,
                const int*   __restrict__ tags,
                const float* __restrict__ mask,
                const float* __restrict__ U,
                float* __restrict__ out)
{
    const int b = blockIdx.x;
    const int j = threadIdx.x;           // column owned by this thread (0..63)
    const int l = j & 31;                // lane
    const int w = j >> 5;                // warp (0,1)

    __shared__ __align__(16) float qA[Cc];
    __shared__ __align__(16) float qB[Cc];
    __shared__ __align__(16) float sU[Cc * Cc];
    __shared__ __align__(16) int   stags[Sc];
    __shared__ __align__(16) float smask[Sc];
    __shared__ float red[2];

    const float* emb = em   + (size_t)b * Sc * Cc;
    const float* mb  = mask + (size_t)b * Sc;

    // ---- rE straight from global U (coalesced per i across threads) ----
    // Issued first so the DRAM latency overlaps the staging below.
    float uu[Cc];
#pragma unroll
    for (int i = 0; i < Cc; ++i) uu[i] = U[i * Cc + j];   // 64 x LDG.32, MLP 64

    // ---- stage sU (for path energy + fallback), tags, mask; seed q ----
    {
        const float4* U4  = (const float4*)U;
        float4*       sU4 = (float4*)sU;
#pragma unroll
        for (int i = 0; i < (Cc * Cc / 4) / Tc; ++i)     // 16 iters
            sU4[j + Tc * i] = U4[j + Tc * i];

        ((int4*)stags)[j]  = ((const int4*)(tags + (size_t)b * Sc))[j];
        ((float4*)smask)[j] = ((const float4*)mb)[j];
    }
    qA[j] = __expf(emb[j]);              // q(0) = exp(em[0])

    // pack exp(U) column into 32 u64 (MUFU burst; overlaps staging)
    unsigned long long rE[32];
#pragma unroll
    for (int p = 0; p < 32; ++p) {
        float e0 = __expf(uu[2 * p + 0]);
        float e1 = __expf(uu[2 * p + 1]);
        PACK2(rE[p], e0, e1);            // {E[2p][j], E[2p+1][j]}
    }

    // mask uniformity from GLOBAL mask (no extra barrier needed)
    int ok = 1;
#pragma unroll
    for (int t = j; t < Sc; t += Tc) ok &= (mb[t] == 1.0f);

    int K = 0;
    // single prologue barrier: orders staging + q seed, reduces ok
    ok = __syncthreads_and(ok);

    if (ok) {
        // ---- fast path: 4-step chunks, renorm once per chunk ----
        float c0 = emb[1 * Cc + j], c1 = emb[2 * Cc + j], c2 = emb[3 * Cc + j];
        float ex0 = __expf(c0), ex1 = __expf(c1), ex2 = __expf(c2);
        float d0 = emb[4 * Cc + j], d1 = emb[5 * Cc + j];
        float d2 = emb[6 * Cc + j], d3 = emb[7 * Cc + j];

        STEP_R(qA, qB, ex0);             // t = 1  (renorm)
        STEP_N(qB, qA, ex1);             // t = 2
        STEP_N(qA, qB, ex2);             // t = 3

        // main chunks t = 4..248: prefetch t+4..t+7 <= 255, guard-free
#pragma unroll 1
        for (int t = 4; t < 252; t += 4) {
            float e0 = __expf(d0), e1 = __expf(d1);
            float e2 = __expf(d2), e3 = __expf(d3);
            float n0 = emb[(t + 4) * Cc + j];
            float n1 = emb[(t + 5) * Cc + j];
            float n2 = emb[(t + 6) * Cc + j];
            float n3 = emb[(t + 7) * Cc + j];

            STEP_R(qB, qA, e0);          // t     (renorm)
            STEP_N(qA, qB, e1);          // t + 1
            STEP_N(qB, qA, e2);          // t + 2
            STEP_N(qA, qB, e3);          // t + 3

            d0 = n0; d1 = n1; d2 = n2; d3 = n3;
        }
        // peeled final chunk t = 252..255 (no prefetch)
        {
            float e0 = __expf(d0), e1 = __expf(d1);
            float e2 = __expf(d2), e3 = __expf(d3);
            STEP_R(qB, qA, e0);          // 252 (renorm)
            STEP_N(qA, qB, e1);          // 253
            STEP_N(qB, qA, e2);          // 254
            STEP_N(qA, qB, e3);          // 255 -> q in qB
        }
    } else {
        // ---- generic masked fallback (never taken in this dataset) ----
        const float* qr = qA; float* qw = qB;
        for (int t = 1; t < Sc; ++t) {
            float m   = smask[t];
            float emv = emb[t * Cc + j];
            float q0  = qr[0];
            int   k   = (int)((__float_as_uint(q0) >> 23) & 0xFF) - 127;
            float sc  = __uint_as_float((unsigned)(127 - k) << 23);
            K += k;

            float s;
            if (m == 1.0f) {
                float a = 0.f;
                for (int i = 0; i < Cc; ++i)
                    a = fmaf(qr[i], __expf(sU[i * Cc + j]), a);
                s = a * __expf(emv);
            } else if (m == 0.0f) {
                float a = 0.f;
                for (int i = 0; i < Cc; ++i) a += qr[i];
                s = a;
            } else {
                float a = 0.f;
                for (int i = 0; i < Cc; ++i)
                    a += qr[i] * __expf((emv + sU[i * Cc + j]) * m);
                s = a;
            }
            qw[j] = s * sc;
            __syncthreads();
            const float* tr = qr; qr = qw; qw = const_cast<float*>(tr);
        }
        // t=255 (odd) wrote qB
    }

    // ---- path energy ----
    float pe = 0.0f;
#pragma unroll
    for (int t = j; t < Sc; t += Tc) {
        float mt = smask[t];
        int   tg = stags[t];
        int   tm = (int)((float)tg * mt);
        pe += emb[t * Cc + tm] * mt;
    }
#pragma unroll
    for (int t = 1 + j; t < Sc; t += Tc) {
        pe += sU[stags[t - 1] * Cc + stags[t]] * smask[t];
    }
#pragma unroll
    for (int o = 16; o > 0; o >>= 1)
        pe += __shfl_xor_sync(0xFFFFFFFFu, pe, o);
    if (l == 0) red[w] = pe;
    __syncthreads();

    // ---- free energy + per-batch result + fused finalize ----
    if (j == 0) {
        float qs = 0.0f;
#pragma unroll
        for (int i = 0; i < Cc; ++i) qs += qB[i];
        float fe = logf(qs) + (float)K * 0.6931471805599453f;
        g_batch_res[b] = fe - (red[0] + red[1]);
        __threadfence();
    }
    __syncthreads();

    if (w == 0) {
        unsigned int old = 0;
        if (l == 0) old = atomicAdd(&g_ticket, 1u);
        old = __shfl_sync(0xFFFFFFFFu, old, 0);
        if (old == Bc - 1) {
            __threadfence();
            float v = 0.0f;
#pragma unroll
            for (int i = 0; i < Bc / 32; ++i) v += g_batch_res[l + 32 * i];
#pragma unroll
            for (int o = 16; o > 0; o >>= 1)
                v += __shfl_xor_sync(0xFFFFFFFFu, v, o);
            if (l == 0) {
                out[0] = v * (1.0f / (float)Bc);
                g_ticket = 0;              // reset for next graph replay
            }
        }
    }
}

extern "C" void kernel_launch(void* const* d_in, const int* in_sizes, int n_in,
                              void* d_out, int out_size)
{
    const float* emissions = (const float*)d_in[0];
    const int*   true_tags = (const int*)  d_in[1];
    const float* mask      = (const float*)d_in[2];
    const float* U         = (const float*)d_in[3];
    float* out = (float*)d_out;

    crf_kernel<<<Bc, Tc>>>(emissions, true_tags, mask, U, out);
}